// round 15
// baseline (speedup 1.0000x reference)
#include <cuda_runtime.h>

// 2-layer LSTM (B=256, T=512, I=64, H=256) + FC(H->1), fp32.
// Persistent kernel, 128 CTAs x 256 threads, CTA tile 32 batch x 16 units.
// Input projections (x@Wih0, h1@Wih1) HOISTED out of the sequential loop as
// parallel FFMA2 GEMMs (8r x 8c tiles) into g_xp; the recurrence consumes them
// as accumulator init. Recurrent GEMM: K=256 (Whh only), 4b x 4c FFMA2 tile,
// 2-way K-split across warp-sets + packed reduction. Flag-based group sync.

#define BB   256
#define TT   512
#define II   64
#define HH   256

#define GRID 128
#define NTHR 256
#define GSIZE 16

typedef unsigned long long ull;

// ---------------- device globals (scratch) ---------------------------------
__device__ float g_hbuf[2][BB * HH];
__device__ float g_h1[(size_t)BB * TT * HH];
__device__ float g_xp[(size_t)BB * TT * 1024];   // hoisted gate projections
__device__ int          g_flag[8 * 32];
__device__ ull          g_gen8[8 * 32];
__device__ unsigned int g_cnt8[8 * 32];

// ---------------- startup atomic barrier (replay-safe) ----------------------
__device__ __forceinline__ void group_barrier_atomic(int g) {
    __syncthreads();
    __threadfence();
    if (threadIdx.x == 0) {
        volatile ull* genp = &g_gen8[g * 32];
        ull my = *genp;
        unsigned prev = atomicAdd(&g_cnt8[g * 32], 1u);
        if (prev == GSIZE - 1u) {
            g_cnt8[g * 32] = 0u;
            __threadfence();
            atomicAdd((ull*)&g_gen8[g * 32], 1ULL);
        } else {
            while (*genp == my) __nanosleep(32);
        }
        __threadfence();
    }
    __syncthreads();
}

// ---------------- flag sync -------------------------------------------------
__device__ __forceinline__ void wait_group(int grp, int target) {
    if (threadIdx.x < GSIZE) {
        volatile int* f = &g_flag[grp * 32 + threadIdx.x];
        while (*f < target) { }
    }
    __syncthreads();
}
__device__ __forceinline__ void publish(int grp, int j, int epoch) {
    __syncthreads();
    if (threadIdx.x == 0) {
        __threadfence();
        *(volatile int*)&g_flag[grp * 32 + j] = epoch;
    }
}

// ---------------- packed f32x2 helpers -------------------------------------
__device__ __forceinline__ void fma2(ull& d, ull a, ull b) {
    asm("fma.rn.f32x2 %0, %1, %2, %0;" : "+l"(d) : "l"(a), "l"(b));
}
__device__ __forceinline__ ull add2(ull a, ull b) {
    ull r;
    asm("add.rn.f32x2 %0, %1, %2;" : "=l"(r) : "l"(a), "l"(b));
    return r;
}
__device__ __forceinline__ ull pack2(float lo, float hi) {
    ull v;
    asm("mov.b64 %0, {%1, %2};" : "=l"(v) : "f"(lo), "f"(hi));
    return v;
}
__device__ __forceinline__ float2 unpack2(ull v) {
    float2 f;
    asm("mov.b64 {%0, %1}, %2;" : "=f"(f.x), "=f"(f.y) : "l"(v));
    return f;
}

// ---------------- activations ----------------------------------------------
__device__ __forceinline__ float fsigmoid(float x) {
    return 1.0f / (1.0f + __expf(-x));
}
__device__ __forceinline__ float ftanh(float x) {
    x = fminf(15.0f, fmaxf(-15.0f, x));
    float t = __expf(2.0f * x);
    return (t - 1.0f) / (t + 1.0f);
}

extern __shared__ float smbuf[];
// Recurrent-phase layout (floats):
//   ws [256][68]=17408 | as [256][36]=9216 | sg [32][68]=2176 | cs 512 |
//   bias 64 | red 2560          total 31936 fl
// Xproj-phase layout: wsx [KIN][68] (<=17408) | ax [64][260]=16640
//   total <= 34048 fl = 136,192 B

// ---------------- hoisted input-projection GEMM -----------------------------
// out g_xp[b][t][gcol] += nothing (pure overwrite), rows = 32b x 8t chunks,
// per-thread tile 8 rows x 8 cols, K chunks of 64.
template<int KIN>
__device__ void xproj_phase(const float* __restrict__ xin,
                            const float* __restrict__ Wih,
                            int mbase, int jbase) {
    float* wsx = smbuf;                 // [KIN][68]
    float* ax  = smbuf + KIN * 68;      // [64][260]
    const int tid = threadIdx.x;

    // weight slice: 64 gate-cols x KIN
    constexpr int K4 = KIN / 4;
    for (int idx = tid; idx < 64 * K4; idx += NTHR) {
        int cc = idx / K4;
        int k  = (idx - cc * K4) * 4;
        int gate = cc >> 4, u = cc & 15;
        float4 w = *(const float4*)(Wih + (gate * HH + jbase + u) * KIN + k);
        wsx[(k + 0) * 68 + cc] = w.x;
        wsx[(k + 1) * 68 + cc] = w.y;
        wsx[(k + 2) * 68 + cc] = w.z;
        wsx[(k + 3) * 68 + cc] = w.w;
    }

    const int r8 = (tid & 31) * 8;              // row group (0..248)
    const int c8 = (tid >> 5) * 8;              // col group (0..56)
    const int gidx = ((c8 >> 4) << 8) + jbase + (c8 & 15);

    for (int tc = 0; tc < TT / 8; tc++) {
        ull acc[4][8];
#pragma unroll
        for (int p = 0; p < 4; p++)
#pragma unroll
            for (int c = 0; c < 8; c++) acc[p][c] = 0ULL;

#pragma unroll 1
        for (int kc = 0; kc < KIN / 64; kc++) {
            __syncthreads();                    // prior ax readers done
            // stage ax[64][260]: 256 rows (32b x 8t) x 64 k
#pragma unroll 4
            for (int i = 0; i < 16; i++) {
                int idx = tid + i * NTHR;
                int r   = idx & 255;
                int k4  = (idx >> 8) * 4;
                float4 a = __ldcg((const float4*)(xin +
                    ((size_t)(mbase + (r >> 3)) * TT + tc * 8 + (r & 7)) * KIN
                    + kc * 64 + k4));
                ax[(k4 + 0) * 260 + r] = a.x;
                ax[(k4 + 1) * 260 + r] = a.y;
                ax[(k4 + 2) * 260 + r] = a.z;
                ax[(k4 + 3) * 260 + r] = a.w;
            }
            __syncthreads();

            const float* ap = ax + r8;
            const float* wp = wsx + (kc * 64) * 68 + c8;
#pragma unroll 8
            for (int kk = 0; kk < 64; kk++) {
                ulonglong2 a01 = *(const ulonglong2*)ap;        // rows r8..r8+3
                ulonglong2 a23 = *(const ulonglong2*)(ap + 4);  // rows r8+4..+7
                float4 w0 = *(const float4*)wp;
                float4 w1 = *(const float4*)(wp + 4);
                ap += 260; wp += 68;
                ull wd[8];
                wd[0] = pack2(w0.x, w0.x); wd[1] = pack2(w0.y, w0.y);
                wd[2] = pack2(w0.z, w0.z); wd[3] = pack2(w0.w, w0.w);
                wd[4] = pack2(w1.x, w1.x); wd[5] = pack2(w1.y, w1.y);
                wd[6] = pack2(w1.z, w1.z); wd[7] = pack2(w1.w, w1.w);
#pragma unroll
                for (int c = 0; c < 8; c++) {
                    fma2(acc[0][c], a01.x, wd[c]);
                    fma2(acc[1][c], a01.y, wd[c]);
                    fma2(acc[2][c], a23.x, wd[c]);
                    fma2(acc[3][c], a23.y, wd[c]);
                }
            }
        }

        // store 8 rows x 8 cols
#pragma unroll
        for (int i = 0; i < 8; i++) {
            int r = r8 + i;
            size_t base = ((size_t)(mbase + (r >> 3)) * TT + tc * 8 + (r & 7))
                          * 1024 + gidx;
            float v[8];
#pragma unroll
            for (int c = 0; c < 8; c++) {
                float2 q = unpack2(acc[i >> 1][c]);
                v[c] = (i & 1) ? q.y : q.x;
            }
            __stcg((float4*)&g_xp[base],     make_float4(v[0], v[1], v[2], v[3]));
            __stcg((float4*)&g_xp[base + 4], make_float4(v[4], v[5], v[6], v[7]));
        }
    }
    __syncthreads();
}

// ---------------- h staging (k-major, batch-contiguous) ----------------------
__device__ __forceinline__ void stage_h(float* as, int mbase,
                                        const float* __restrict__ hr) {
    const int bb  = threadIdx.x >> 3;
    const int kof = (threadIdx.x & 7) * 4;
#pragma unroll
    for (int c = 0; c < 8; c++) {
        int k = c * 32 + kof;
        float4 a = __ldcg((const float4*)(hr + (mbase + bb) * HH + k));
        as[(k + 0) * 36 + bb] = a.x;
        as[(k + 1) * 36 + bb] = a.y;
        as[(k + 2) * 36 + bb] = a.z;
        as[(k + 3) * 36 + bb] = a.w;
    }
}

// ---------------- recurrent GEMM over k-range, depth-2 pipelined -------------
#define GMATH(AV, W) do {                                                     \
    ull wxx = pack2((W).x, (W).x), wyy = pack2((W).y, (W).y);                 \
    ull wzz = pack2((W).z, (W).z), www = pack2((W).w, (W).w);                 \
    fma2(acc[0][0], (AV).x, wxx); fma2(acc[0][1], (AV).x, wyy);               \
    fma2(acc[0][2], (AV).x, wzz); fma2(acc[0][3], (AV).x, www);               \
    fma2(acc[1][0], (AV).y, wxx); fma2(acc[1][1], (AV).y, wyy);               \
    fma2(acc[1][2], (AV).y, wzz); fma2(acc[1][3], (AV).y, www);               \
} while (0)

__device__ __forceinline__ void gemm_range(ull (&acc)[2][4],
                                           const float* __restrict__ as,
                                           const float* __restrict__ ws,
                                           int k0, int k1, int b4, int c4) {
    const float* ap = as + k0 * 36 + b4;
    const float* wp = ws + k0 * 68 + c4;
    const int n = k1 - k0;
    ulonglong2 av0 = *(const ulonglong2*)ap;
    float4     w0  = *(const float4*)wp;
    ulonglong2 av1 = *(const ulonglong2*)(ap + 36);
    float4     w1  = *(const float4*)(wp + 68);
    ap += 72; wp += 136;
#pragma unroll 8
    for (int kk = 0; kk < n - 2; kk++) {
        ulonglong2 av2 = *(const ulonglong2*)ap;
        float4     w2  = *(const float4*)wp;
        ap += 36; wp += 68;
        GMATH(av0, w0);
        av0 = av1; w0 = w1;
        av1 = av2; w1 = w2;
    }
    GMATH(av0, w0);
    GMATH(av1, w1);
}

// ---------------- one LSTM layer -------------------------------------------
template<int KIN, bool ARCHIVE>
__device__ void run_layer(int base,
                          const float* __restrict__ xsrc,   // xproj input
                          const float* __restrict__ Wih,
                          const float* __restrict__ Whh,
                          const float* __restrict__ bih,
                          const float* __restrict__ bhh) {
    float* ws   = smbuf;                     // [256][68]
    float* as   = smbuf + 17408;             // [256][36]
    float* sg   = smbuf + 26624;             // [32][68]
    float* cs   = smbuf + 28800;             // [512]
    float* bias = smbuf + 29312;             // [64]
    ull*   red  = (ull*)(smbuf + 29376);     // [128*10] ull

    const int tid   = threadIdx.x;
    const int grp   = blockIdx.x >> 4;
    const int jj    = blockIdx.x & 15;
    const int mbase = grp * 32;
    const int jbase = jj * 16;

    wait_group(grp, base);                   // layer entry gate

    // ---- hoisted input projection for this layer ----
    xproj_phase<KIN>(xsrc, Wih, mbase, jbase);

    // ---- init recurrent state: Whh slice -> smem, zero c / h(-1), biases ----
    for (int idx = tid; idx < 64 * (HH / 4); idx += NTHR) {
        int cc = idx / (HH / 4);
        int k  = (idx - cc * (HH / 4)) * 4;
        int gate = cc >> 4, u = cc & 15;
        float4 w = *(const float4*)(Whh + (gate * HH + jbase + u) * HH + k);
        ws[(k + 0) * 68 + cc] = w.x;
        ws[(k + 1) * 68 + cc] = w.y;
        ws[(k + 2) * 68 + cc] = w.z;
        ws[(k + 3) * 68 + cc] = w.w;
    }
    for (int idx = tid; idx < 512; idx += NTHR) {
        cs[idx] = 0.0f;
        int bb = idx >> 4, u = idx & 15;
        __stcg(&g_hbuf[0][(mbase + bb) * HH + jbase + u], 0.0f);
    }
    if (tid < 64) {
        int gate = tid >> 4, u = tid & 15;
        bias[tid] = bih[gate * HH + jbase + u] + bhh[gate * HH + jbase + u];
    }
    publish(grp, jj, base + 1);

    const int sset = tid >> 7;
    const int stid = tid & 127;
    const int b4 = (stid & 7) * 4;
    const int c4 = (stid >> 3) * 4;
    const int gidx = ((c4 >> 4) << 8) + jbase + (c4 & 15);
    const int h0 = sset * (HH / 2), h1e = h0 + HH / 2;

    for (int t = 0; t < TT; t++) {
        const float* hr = g_hbuf[t & 1];
        float*       hw = g_hbuf[(t & 1) ^ 1];

        // preload this thread's xproj tile (independent of h; covers wait)
        float4 xr[4];
        if (sset == 0) {
#pragma unroll
            for (int i = 0; i < 4; i++)
                xr[i] = __ldcg((const float4*)&g_xp[
                    ((size_t)(mbase + b4 + i) * TT + t) * 1024 + gidx]);
        }

        wait_group(grp, base + 1 + t);
        stage_h(as, mbase, hr);
        __syncthreads();

        // acc init: set 0 starts from xproj partials, set 1 from zero
        ull acc[2][4];
        if (sset == 0) {
#pragma unroll
            for (int p = 0; p < 2; p++) {
                const float* r0 = (const float*)&xr[2 * p];
                const float* r1 = (const float*)&xr[2 * p + 1];
#pragma unroll
                for (int c = 0; c < 4; c++) acc[p][c] = pack2(r0[c], r1[c]);
            }
        } else {
#pragma unroll
            for (int p = 0; p < 2; p++)
#pragma unroll
                for (int c = 0; c < 4; c++) acc[p][c] = 0ULL;
        }

        gemm_range(acc, as, ws, h0, h1e, b4, c4);

        // cross-set reduction
        if (sset == 1) {
#pragma unroll
            for (int p = 0; p < 2; p++)
#pragma unroll
                for (int c = 0; c < 4; c++)
                    red[stid * 10 + p * 4 + c] = acc[p][c];
        }
        __syncthreads();
        if (sset == 0) {
#pragma unroll
            for (int p = 0; p < 2; p++)
#pragma unroll
                for (int c = 0; c < 4; c++)
                    acc[p][c] = add2(acc[p][c], red[stid * 10 + p * 4 + c]);
#pragma unroll
            for (int p = 0; p < 2; p++) {
                float2 f0 = unpack2(acc[p][0]);
                float2 f1 = unpack2(acc[p][1]);
                float2 f2 = unpack2(acc[p][2]);
                float2 f3 = unpack2(acc[p][3]);
                *(float4*)&sg[(b4 + 2 * p + 0) * 68 + c4] =
                    make_float4(f0.x, f1.x, f2.x, f3.x);
                *(float4*)&sg[(b4 + 2 * p + 1) * 68 + c4] =
                    make_float4(f0.y, f1.y, f2.y, f3.y);
            }
        }
        __syncthreads();

        // ---- LSTM pointwise: 512 (b,u) pairs / 256 threads ----
#pragma unroll
        for (int r = 0; r < 2; r++) {
            int pair = tid * 2 + r;
            int bb = pair >> 4;
            int u  = pair & 15;
            float pi = sg[bb * 68 + u]      + bias[u];
            float pf = sg[bb * 68 + 16 + u] + bias[16 + u];
            float pg = sg[bb * 68 + 32 + u] + bias[32 + u];
            float po = sg[bb * 68 + 48 + u] + bias[48 + u];
            float ig = fsigmoid(pi);
            float fg = fsigmoid(pf);
            float gg = ftanh(pg);
            float og = fsigmoid(po);
            float cv = fg * cs[bb * 16 + u] + ig * gg;
            cs[bb * 16 + u] = cv;
            float hv = og * ftanh(cv);
            __stcg(&hw[(mbase + bb) * HH + jbase + u], hv);
            if (ARCHIVE)
                __stcg(&g_h1[(size_t)((mbase + bb) * TT + t) * HH + jbase + u], hv);
        }

        publish(grp, jj, base + 2 + t);
    }
}

// ---------------- full model -----------------------------------------------
__global__ void __launch_bounds__(NTHR, 1)
lstm_persistent_kernel(const float* __restrict__ x,
                       const float* __restrict__ Wih0, const float* __restrict__ Whh0,
                       const float* __restrict__ bih0, const float* __restrict__ bhh0,
                       const float* __restrict__ Wih1, const float* __restrict__ Whh1,
                       const float* __restrict__ bih1, const float* __restrict__ bhh1,
                       const float* __restrict__ Wfc,  const float* __restrict__ bfc,
                       float* __restrict__ out) {
    const int grp = blockIdx.x >> 4;
    const int jj  = blockIdx.x & 15;

    if (threadIdx.x == 0)
        *(volatile int*)&g_flag[grp * 32 + jj] = 0;
    group_barrier_atomic(grp);

    run_layer<II, true >(0,      x,    Wih0, Whh0, bih0, bhh0);  // epochs 1..513
    run_layer<HH, false>(TT + 1, g_h1, Wih1, Whh1, bih1, bhh1);  // 514..1026

    if (jj == 0) {
        wait_group(grp, 2 * TT + 2);
        int mbase = grp * 32;
        for (int bb = threadIdx.x; bb < 32; bb += NTHR) {
            float s = bfc[0];
#pragma unroll 8
            for (int j = 0; j < HH; j++)
                s += __ldcg(&g_hbuf[0][(mbase + bb) * HH + j]) * Wfc[j];
            out[mbase + bb] = s;
        }
    }
}

// ---------------- harness entry --------------------------------------------
extern "C" void kernel_launch(void* const* d_in, const int* in_sizes, int n_in,
                              void* d_out, int out_size) {
    (void)in_sizes; (void)n_in; (void)out_size;
    const float* x    = (const float*)d_in[0];
    const float* Wih0 = (const float*)d_in[1];
    const float* Whh0 = (const float*)d_in[2];
    const float* bih0 = (const float*)d_in[3];
    const float* bhh0 = (const float*)d_in[4];
    const float* Wih1 = (const float*)d_in[5];
    const float* Whh1 = (const float*)d_in[6];
    const float* bih1 = (const float*)d_in[7];
    const float* bhh1 = (const float*)d_in[8];
    const float* Wfc  = (const float*)d_in[9];
    const float* bfc  = (const float*)d_in[10];

    // max(xproj phase: (256*68 + 64*260) fl, recurrent: 31936 fl) = 34048 fl
    const int smem_bytes = 34048 * 4;        // 136,192 B
    cudaFuncSetAttribute(lstm_persistent_kernel,
                         cudaFuncAttributeMaxDynamicSharedMemorySize, smem_bytes);

    lstm_persistent_kernel<<<GRID, NTHR, smem_bytes>>>(
        x, Wih0, Whh0, bih0, bhh0,
        Wih1, Whh1, bih1, bhh1,
        Wfc, bfc, (float*)d_out);
}

// round 17
// speedup vs baseline: 1.0512x; 1.0512x over previous
#include <cuda_runtime.h>

// 2-layer LSTM (B=256, T=512, I=64, H=256) + FC(H->1), fp32.
// Persistent kernel, 128 CTAs x 512 threads, CTA tile 32 batch x 16 units.
// Weights resident in smem. 4b x 4c FFMA2 tile, depth-2 pipelined.
// 4-way K-split across warp-sets (4 warps/SMSP) + packed f32x2 reduction.
// x-part GEMM before the group wait; one-way flag group sync.

#define BB   256
#define TT   512
#define II   64
#define HH   256

#define GRID 128
#define NTHR 512
#define GSIZE 16

typedef unsigned long long ull;

// ---------------- device globals (scratch) ---------------------------------
__device__ float g_hbuf[2][BB * HH];
__device__ float g_h1[(size_t)BB * TT * HH];
__device__ int          g_flag[8 * 32];
__device__ ull          g_gen8[8 * 32];
__device__ unsigned int g_cnt8[8 * 32];

// ---------------- startup atomic barrier (replay-safe) ----------------------
__device__ __forceinline__ void group_barrier_atomic(int g) {
    __syncthreads();
    __threadfence();
    if (threadIdx.x == 0) {
        volatile ull* genp = &g_gen8[g * 32];
        ull my = *genp;
        unsigned prev = atomicAdd(&g_cnt8[g * 32], 1u);
        if (prev == GSIZE - 1u) {
            g_cnt8[g * 32] = 0u;
            __threadfence();
            atomicAdd((ull*)&g_gen8[g * 32], 1ULL);
        } else {
            while (*genp == my) __nanosleep(32);
        }
        __threadfence();
    }
    __syncthreads();
}

// ---------------- flag sync -------------------------------------------------
__device__ __forceinline__ void wait_group(int grp, int target) {
    if (threadIdx.x < GSIZE) {
        volatile int* f = &g_flag[grp * 32 + threadIdx.x];
        while (*f < target) { }
    }
    __syncthreads();
}
__device__ __forceinline__ void publish(int grp, int j, int epoch) {
    __syncthreads();
    if (threadIdx.x == 0) {
        __threadfence();
        *(volatile int*)&g_flag[grp * 32 + j] = epoch;
    }
}

// ---------------- packed f32x2 helpers -------------------------------------
__device__ __forceinline__ void fma2(ull& d, ull a, ull b) {
    asm("fma.rn.f32x2 %0, %1, %2, %0;" : "+l"(d) : "l"(a), "l"(b));
}
__device__ __forceinline__ ull add2(ull a, ull b) {
    ull r;
    asm("add.rn.f32x2 %0, %1, %2;" : "=l"(r) : "l"(a), "l"(b));
    return r;
}
__device__ __forceinline__ ull pack2(float lo, float hi) {
    ull v;
    asm("mov.b64 %0, {%1, %2};" : "=l"(v) : "f"(lo), "f"(hi));
    return v;
}
__device__ __forceinline__ float2 unpack2(ull v) {
    float2 f;
    asm("mov.b64 {%0, %1}, %2;" : "=f"(f.x), "=f"(f.y) : "l"(v));
    return f;
}

// ---------------- activations ----------------------------------------------
__device__ __forceinline__ float fsigmoid(float x) {
    return 1.0f / (1.0f + __expf(-x));
}
__device__ __forceinline__ float ftanh(float x) {
    x = fminf(15.0f, fmaxf(-15.0f, x));
    float t = __expf(2.0f * x);
    return (t - 1.0f) / (t + 1.0f);
}

// Dynamic smem (floats), K = HH + KIN:
//   ws  [K][68]  | as [K][36] (+PAD) | sg [32][68] | cs [512] | bias [64]
//   red (3 sets x 128 thr x 8 ull = 6144 fl) overlays as x-rows (+PAD).
extern __shared__ float smbuf[];

// ---------------- A staging over chunk range [c0, c1) -----------------------
template<int KIN>
__device__ __forceinline__ void stage_A(float* as, int c0, int c1, int t, int mbase,
                                        const float* __restrict__ hr,
                                        const float* __restrict__ xin) {
    const int n4 = (c1 - c0) * 256;           // float4s in range
    for (int i = threadIdx.x; i < n4; i += NTHR) {
        int r  = i & 255;
        int c  = c0 + (i >> 8);
        int bb = r >> 3;
        int k  = c * 32 + (r & 7) * 4;
        const float* src;
        if (k < HH) src = hr + (mbase + bb) * HH + k;
        else {
            if (KIN == HH)
                src = xin + ((size_t)(mbase + bb) * TT + t) * HH + (k - HH);
            else
                src = xin + ((size_t)(mbase + bb) * TT + t) * II + (k - HH);
        }
        float4 a = __ldcg((const float4*)src);
        as[(k + 0) * 36 + bb] = a.x;
        as[(k + 1) * 36 + bb] = a.y;
        as[(k + 2) * 36 + bb] = a.z;
        as[(k + 3) * 36 + bb] = a.w;
    }
}

// ---------------- GEMM over k-range [k0, k1), depth-2 pipelined -------------
#define GMATH(AV, W) do {                                                     \
    ull wxx = pack2((W).x, (W).x), wyy = pack2((W).y, (W).y);                 \
    ull wzz = pack2((W).z, (W).z), www = pack2((W).w, (W).w);                 \
    fma2(acc[0][0], (AV).x, wxx); fma2(acc[0][1], (AV).x, wyy);               \
    fma2(acc[0][2], (AV).x, wzz); fma2(acc[0][3], (AV).x, www);               \
    fma2(acc[1][0], (AV).y, wxx); fma2(acc[1][1], (AV).y, wyy);               \
    fma2(acc[1][2], (AV).y, wzz); fma2(acc[1][3], (AV).y, www);               \
} while (0)

__device__ __forceinline__ void gemm_range(ull (&acc)[2][4],
                                           const float* __restrict__ as,
                                           const float* __restrict__ ws,
                                           int k0, int k1, int b4, int c4) {
    const float* ap = as + k0 * 36 + b4;
    const float* wp = ws + k0 * 68 + c4;
    const int n = k1 - k0;
    ulonglong2 av0 = *(const ulonglong2*)ap;
    float4     w0  = *(const float4*)wp;
    ulonglong2 av1 = *(const ulonglong2*)(ap + 36);
    float4     w1  = *(const float4*)(wp + 68);
    ap += 72; wp += 136;
#pragma unroll 8
    for (int kk = 0; kk < n - 2; kk++) {
        ulonglong2 av2 = *(const ulonglong2*)ap;
        float4     w2  = *(const float4*)wp;
        ap += 36; wp += 68;
        GMATH(av0, w0);
        av0 = av1; w0 = w1;
        av1 = av2; w1 = w2;
    }
    GMATH(av0, w0);
    GMATH(av1, w1);
}

// ---------------- one LSTM layer -------------------------------------------
template<int KIN, bool ARCHIVE>
__device__ void run_layer(int base, const float* __restrict__ xin,
                          const float* __restrict__ Wih,
                          const float* __restrict__ Whh,
                          const float* __restrict__ bih,
                          const float* __restrict__ bhh) {
    constexpr int K = HH + KIN;
    // red needs 6144 floats starting at as + HH*36; pad so sg is clear of it.
    constexpr int XFL = (K - HH) * 36;
    constexpr int PAD = (6144 > XFL) ? (6144 - XFL) : 0;
    float* ws   = smbuf;                       // [K][68]
    float* as   = smbuf + K * 68;              // [K][36]
    float* sg   = as + K * 36 + PAD;           // [32][68]
    float* cs   = sg + 32 * 68;                // [512]
    float* bias = cs + 512;                    // [64]
    ull*   red  = (ull*)(as + HH * 36);        // 3*128*8 ull, overlays x-rows

    const int tid   = threadIdx.x;
    const int grp   = blockIdx.x >> 4;
    const int jj    = blockIdx.x & 15;
    const int mbase = grp * 32;
    const int jbase = jj * 16;

    wait_group(grp, base);                     // layer entry gate

    // ---- init: weight slice -> smem, zero c / h(-1), biases ----
    constexpr int K4 = K / 4;
    for (int idx = tid; idx < 64 * K4; idx += NTHR) {
        int cc = idx / K4;
        int k  = (idx - cc * K4) * 4;
        int gate = cc >> 4, u = cc & 15;
        int grow = gate * HH + jbase + u;
        const float* src = (k < HH) ? (Whh + grow * HH + k)
                                    : (Wih + grow * KIN + k - HH);
        float4 w = *(const float4*)src;
        ws[(k + 0) * 68 + cc] = w.x;
        ws[(k + 1) * 68 + cc] = w.y;
        ws[(k + 2) * 68 + cc] = w.z;
        ws[(k + 3) * 68 + cc] = w.w;
    }
    for (int idx = tid; idx < 512; idx += NTHR) {
        cs[idx] = 0.0f;
        int bb = idx >> 4, u = idx & 15;
        __stcg(&g_hbuf[0][(mbase + bb) * HH + jbase + u], 0.0f);
    }
    if (tid < 64) {
        int gate = tid >> 4, u = tid & 15;
        int grow = gate * HH + jbase + u;
        bias[tid] = bih[grow] + bhh[grow];
    }
    publish(grp, jj, base + 1);

    // prologue: stage x-part for t=0
    stage_A<KIN>(as, HH / 32, K / 32, 0, mbase, nullptr, xin);
    __syncthreads();

    const int sset = tid >> 7;                 // warp-set 0..3
    const int stid = tid & 127;
    const int b4 = (stid & 7) * 4;
    const int c4 = (stid >> 3) * 4;
    constexpr int XQ = KIN / 4;                // x k-range per set
    const int x0 = HH + sset * XQ, x1 = x0 + XQ;
    const int h0 = sset * (HH / 4), h1e = h0 + HH / 4;

    for (int t = 0; t < TT; t++) {
        const float* hr = g_hbuf[t & 1];
        float*       hw = g_hbuf[(t & 1) ^ 1];

        ull acc[2][4];
#pragma unroll
        for (int p = 0; p < 2; p++)
#pragma unroll
            for (int c = 0; c < 4; c++) acc[p][c] = 0ULL;

        // x-part (independent of h(t-1)) — absorbs group skew
        gemm_range(acc, as, ws, x0, x1, b4, c4);

        // wait for h(t-1), stage it (all 512 threads), do this set's h quarter
        wait_group(grp, base + 1 + t);
        stage_A<KIN>(as, 0, HH / 32, t, mbase, hr, xin);
        __syncthreads();
        gemm_range(acc, as, ws, h0, h1e, b4, c4);

        // ---- cross-set reduction: sets 1..3 store, set 0 sums (x-rows are
        //      fully consumed before this point; re-staged after sg sync) ----
        if (sset != 0) {
            ull* rp = red + (size_t)(sset - 1) * 1024 + stid * 8;
#pragma unroll
            for (int p = 0; p < 2; p++)
#pragma unroll
                for (int c = 0; c < 4; c++)
                    rp[p * 4 + c] = acc[p][c];
        }
        __syncthreads();
        if (sset == 0) {
#pragma unroll
            for (int s = 0; s < 3; s++) {
                const ull* rp = red + (size_t)s * 1024 + stid * 8;
#pragma unroll
                for (int p = 0; p < 2; p++)
#pragma unroll
                    for (int c = 0; c < 4; c++)
                        acc[p][c] = add2(acc[p][c], rp[p * 4 + c]);
            }
#pragma unroll
            for (int p = 0; p < 2; p++) {
                float2 f0 = unpack2(acc[p][0]);
                float2 f1 = unpack2(acc[p][1]);
                float2 f2 = unpack2(acc[p][2]);
                float2 f3 = unpack2(acc[p][3]);
                *(float4*)&sg[(b4 + 2 * p + 0) * 68 + c4] =
                    make_float4(f0.x, f1.x, f2.x, f3.x);
                *(float4*)&sg[(b4 + 2 * p + 1) * 68 + c4] =
                    make_float4(f0.y, f1.y, f2.y, f3.y);
            }
        }
        __syncthreads();

        // ---- LSTM pointwise: 512 (b,u) pairs / 512 threads ----
        {
            int bb = tid >> 4;
            int u  = tid & 15;
            float pi = sg[bb * 68 + u]      + bias[u];
            float pf = sg[bb * 68 + 16 + u] + bias[16 + u];
            float pg = sg[bb * 68 + 32 + u] + bias[32 + u];
            float po = sg[bb * 68 + 48 + u] + bias[48 + u];
            float ig = fsigmoid(pi);
            float fg = fsigmoid(pf);
            float gg = ftanh(pg);
            float og = fsigmoid(po);
            float cv = fg * cs[bb * 16 + u] + ig * gg;
            cs[bb * 16 + u] = cv;
            float hv = og * ftanh(cv);
            __stcg(&hw[(mbase + bb) * HH + jbase + u], hv);
            if (ARCHIVE)
                __stcg(&g_h1[(size_t)((mbase + bb) * TT + t) * HH + jbase + u], hv);
        }

        // prefetch x-part for t+1 (after red reads: protected by sync above)
        if (t + 1 < TT)
            stage_A<KIN>(as, HH / 32, K / 32, t + 1, mbase, nullptr, xin);

        publish(grp, jj, base + 2 + t);
    }
}

// ---------------- full model -----------------------------------------------
__global__ void __launch_bounds__(NTHR, 1)
lstm_persistent_kernel(const float* __restrict__ x,
                       const float* __restrict__ Wih0, const float* __restrict__ Whh0,
                       const float* __restrict__ bih0, const float* __restrict__ bhh0,
                       const float* __restrict__ Wih1, const float* __restrict__ Whh1,
                       const float* __restrict__ bih1, const float* __restrict__ bhh1,
                       const float* __restrict__ Wfc,  const float* __restrict__ bfc,
                       float* __restrict__ out) {
    const int grp = blockIdx.x >> 4;
    const int jj  = blockIdx.x & 15;

    if (threadIdx.x == 0)
        *(volatile int*)&g_flag[grp * 32 + jj] = 0;
    group_barrier_atomic(grp);

    run_layer<II, true >(0,      x,    Wih0, Whh0, bih0, bhh0);  // epochs 1..513
    run_layer<HH, false>(TT + 1, g_h1, Wih1, Whh1, bih1, bhh1);  // 514..1026

    if (jj == 0) {
        wait_group(grp, 2 * TT + 2);
        int mbase = grp * 32;
        for (int bb = threadIdx.x; bb < 32; bb += NTHR) {
            float s = bfc[0];
#pragma unroll 8
            for (int j = 0; j < HH; j++)
                s += __ldcg(&g_hbuf[0][(mbase + bb) * HH + j]) * Wfc[j];
            out[mbase + bb] = s;
        }
    }
}

// ---------------- harness entry --------------------------------------------
extern "C" void kernel_launch(void* const* d_in, const int* in_sizes, int n_in,
                              void* d_out, int out_size) {
    (void)in_sizes; (void)n_in; (void)out_size;
    const float* x    = (const float*)d_in[0];
    const float* Wih0 = (const float*)d_in[1];
    const float* Whh0 = (const float*)d_in[2];
    const float* bih0 = (const float*)d_in[3];
    const float* bhh0 = (const float*)d_in[4];
    const float* Wih1 = (const float*)d_in[5];
    const float* Whh1 = (const float*)d_in[6];
    const float* bih1 = (const float*)d_in[7];
    const float* bhh1 = (const float*)d_in[8];
    const float* Wfc  = (const float*)d_in[9];
    const float* bfc  = (const float*)d_in[10];

    // L1 footprint: 512*68 + 512*36 + 32*68 + 512 + 64 = 56000 floats
    const int smem_bytes = 56000 * 4;          // 224,000 B
    cudaFuncSetAttribute(lstm_persistent_kernel,
                         cudaFuncAttributeMaxDynamicSharedMemorySize, smem_bytes);

    lstm_persistent_kernel<<<GRID, NTHR, smem_bytes>>>(
        x, Wih0, Whh0, bih0, bhh0,
        Wih1, Whh1, bih1, bhh1,
        Wfc, bfc, (float*)d_out);
}